// round 7
// baseline (speedup 1.0000x reference)
#include <cuda_runtime.h>
#include <cuda_bf16.h>
#include <cstdint>

#define B_SZ 1024

// hidden activations, [b][e][j] layout
__device__ float g_h1[B_SZ * 64 * 64];
__device__ float g_h2[B_SZ * 64 * 64];
// W fragment-linear: per 64-K chunk: [s(4)][nfrag(8)][lane(32)] uint4{hi01,hi23,lo01,lo23}
__device__ __align__(16) uint4 g_Wf0[16 * 1024];
__device__ __align__(16) uint4 g_Wf1[32 * 1024];
// S matrices (direct path)
__device__ float g_S0[B_SZ * 1024];
__device__ float g_S1[B_SZ * 2048];
__device__ float g_S2[B_SZ * 2048];
// k-split partials
__device__ float g_part[8 * B_SZ * 256];

__device__ __forceinline__ uint32_t smem_u32(const void* p) {
    uint32_t a;
    asm("{ .reg .u64 t; cvta.to.shared.u64 t, %1; cvt.u32.u64 %0, t; }" : "=r"(a) : "l"(p));
    return a;
}
__device__ __forceinline__ uint32_t pack_hi(float a, float b) {
    return __byte_perm(__float_as_uint(a), __float_as_uint(b), 0x7632);
}
__device__ __forceinline__ uint32_t pack_lo(float a, float b) {
    float la = a - __uint_as_float(__float_as_uint(a) & 0xFFFF0000u);
    float lb = b - __uint_as_float(__float_as_uint(b) & 0xFFFF0000u);
    uint32_t r;
    asm("cvt.rn.bf16x2.f32 %0, %1, %2;" : "=r"(r) : "f"(lb), "f"(la));
    return r;
}
__device__ __forceinline__ void mma16816(float* c, const uint32_t* a,
                                         uint32_t b0, uint32_t b1) {
    asm volatile(
        "mma.sync.aligned.m16n8k16.row.col.f32.bf16.bf16.f32 "
        "{%0,%1,%2,%3}, {%4,%5,%6,%7}, {%8,%9}, {%0,%1,%2,%3};"
        : "+f"(c[0]), "+f"(c[1]), "+f"(c[2]), "+f"(c[3])
        : "r"(a[0]), "r"(a[1]), "r"(a[2]), "r"(a[3]), "r"(b0), "r"(b1));
}

// ---------------------------------------------------------------------------
__global__ void __launch_bounds__(256)
wfrag(const float* __restrict__ W, uint4* __restrict__ out) {
    const int c = blockIdx.x;
    for (int t = threadIdx.x; t < 1024; t += 256) {
        int s = t >> 8, f = (t >> 5) & 7, lane = t & 31;
        int n = f * 8 + (lane >> 2);
        int r = c * 64 + s * 16 + (lane & 3) * 4;
        float w0 = W[(r    ) * 128 + n], w1 = W[(r + 1) * 128 + n];
        float w2 = W[(r + 2) * 128 + n], w3 = W[(r + 3) * 128 + n];
        uint4 o;
        o.x = pack_hi(w0, w1);
        o.y = pack_hi(w2, w3);
        o.z = pack_lo(w0, w1);
        o.w = pack_lo(w2, w3);
        out[c * 1024 + t] = o;
    }
}

// ---------------------------------------------------------------------------
// Hidden layer via mma.sync (bf16 split), register-pipelined, triple-buffered.
// hout [b][e][n], n<64. grid=512, block=256 (8 warps = 4m x 2n), 2 CTA/SM.
// ---------------------------------------------------------------------------
template<int FI>
__global__ void __launch_bounds__(256, 2)
cin_mma(const float* __restrict__ x, const float* __restrict__ h,
        const uint4* __restrict__ Wf, const float* __restrict__ bias,
        float* __restrict__ hout)
{
    constexpr int NC = (32 * FI) / 64;   // 64-K chunks (16 or 32)
    constexpr int OFF_XS = 256;
    constexpr int OFF_HS = OFF_XS + 128 * 33 * 4;   // 17152
    constexpr int OFF_B  = OFF_HS + 128 * 80 * 4;   // 58112; B: 3 x 16384

    extern __shared__ char smem[];
    float* bias_s = (float*)smem;
    float* xs = (float*)(smem + OFF_XS);   // [128][33]
    float* hs = (float*)(smem + OFF_HS);   // [128][80]
    const uint32_t Bsm = smem_u32(smem) + OFF_B;

    const int tid  = threadIdx.x;
    const int lane = tid & 31;
    const int wid  = tid >> 5;
    const int wm   = wid & 3, wn = wid >> 2;
    const int tq   = lane & 3;
    const int q2   = tq * 2;
    const int b0   = blockIdx.x * 2;

    if (tid < 64) bias_s[tid] = bias[tid];
    for (int idx = tid; idx < 4096; idx += 256) {
        int i = idx >> 7, mr = idx & 127;
        xs[mr * 33 + i] = x[((b0 + (mr >> 6)) * 32 + i) * 64 + (mr & 63)];
    }
    if (FI == 64) {
#pragma unroll
        for (int r = 0; r < 8; ++r) {
            int idx = tid + r * 256;
            int row = idx >> 4, c4 = idx & 15;
            float4 v = *(const float4*)&h[((b0 + (row >> 6)) * 64 + (row & 63)) * 64 + c4 * 4];
            *(float4*)&hs[row * 80 + c4 * 4] = v;
        }
    } else {
#pragma unroll
        for (int r = 0; r < 16; ++r) {
            int idx = tid + r * 256;
            int j = idx >> 7, mr = idx & 127;
            hs[mr * 80 + j] = h[((b0 + (mr >> 6)) * 32 + j) * 64 + (mr & 63)];
        }
    }

    // prefetch B chunks 0,1 into buffers 0,1
#pragma unroll
    for (int pc = 0; pc < 2; ++pc) {
#pragma unroll
        for (int r = 0; r < 4; ++r) {
            uint32_t dst = Bsm + pc * 16384u + (uint32_t)(tid + r * 256) * 16u;
            const uint4* src = Wf + pc * 1024 + tid + r * 256;
            asm volatile("cp.async.cg.shared.global [%0], [%1], 16;"
                         :: "r"(dst), "l"(src));
        }
        asm volatile("cp.async.commit_group;");
    }

    float acc[2][4][4];
#pragma unroll
    for (int mf = 0; mf < 2; ++mf)
#pragma unroll
        for (int nf = 0; nf < 4; ++nf)
#pragma unroll
            for (int r = 0; r < 4; ++r) acc[mf][nf][r] = 0.f;

    const int ra_base = wm * 32 + (lane >> 2);
    int buf = 0;   // buffer index of current chunk (mod 3)

    for (int c = 0; c < NC; ++c) {
        asm volatile("cp.async.wait_group 1;" ::: "memory");
        __syncthreads();

        // issue prefetch for chunk c+2 into the free buffer (buf+2)%3
        {
            int nb = buf + 2; if (nb >= 3) nb -= 3;
            if (c + 2 < NC) {
#pragma unroll
                for (int r = 0; r < 4; ++r) {
                    uint32_t dst = Bsm + (uint32_t)nb * 16384u
                                 + (uint32_t)(tid + r * 256) * 16u;
                    const uint4* src = Wf + (c + 2) * 1024 + tid + r * 256;
                    asm volatile("cp.async.cg.shared.global [%0], [%1], 16;"
                                 :: "r"(dst), "l"(src));
                }
            }
            asm volatile("cp.async.commit_group;");
        }

        const uint32_t Bb = Bsm + (uint32_t)buf * 16384u;

        float xreg[2][2][2];
#pragma unroll
        for (int mf = 0; mf < 2; ++mf) {
            const int ra = ra_base + mf * 16, rb = ra + 8;
            if (FI == 64) {
                xreg[mf][0][0] = xs[ra * 33 + c];
                xreg[mf][1][0] = xs[rb * 33 + c];
                xreg[mf][0][1] = xreg[mf][0][0];
                xreg[mf][1][1] = xreg[mf][1][0];
            } else {
                xreg[mf][0][0] = xs[ra * 33 + 2 * c];
                xreg[mf][1][0] = xs[rb * 33 + 2 * c];
                xreg[mf][0][1] = xs[ra * 33 + 2 * c + 1];
                xreg[mf][1][1] = xs[rb * 33 + 2 * c + 1];
            }
        }

        // pipelined fragment banks
        uint4 Bf[2][4];
        uint32_t ah[2][2][4], al[2][2][4];

        // -------- prep for a given stage into bank p --------
#define PREP_STAGE(ss, p)                                                     \
        {                                                                     \
            _Pragma("unroll")                                                 \
            for (int nf = 0; nf < 4; ++nf) {                                  \
                uint32_t addr = Bb + (uint32_t)((((ss) * 8) + wn * 4 + nf) * 32 + lane) * 16u; \
                asm volatile("ld.shared.v4.u32 {%0,%1,%2,%3}, [%4];"          \
                             : "=r"(Bf[p][nf].x), "=r"(Bf[p][nf].y),          \
                               "=r"(Bf[p][nf].z), "=r"(Bf[p][nf].w)           \
                             : "r"(addr));                                    \
            }                                                                 \
            const int jcol = ((FI == 64) ? (ss) * 16 : ((ss) & 1) * 16) + 4 * tq; \
            const int isub = (FI == 64) ? 0 : ((ss) >> 1);                    \
            _Pragma("unroll")                                                 \
            for (int mf = 0; mf < 2; ++mf) {                                  \
                const int ra = ra_base + mf * 16, rb = ra + 8;                \
                float4 ha = *(const float4*)&hs[ra * 80 + jcol];              \
                float4 hb = *(const float4*)&hs[rb * 80 + jcol];              \
                float xa = xreg[mf][0][isub], xb = xreg[mf][1][isub];         \
                float pa0 = xa * ha.x, pa1 = xa * ha.y, pa2 = xa * ha.z, pa3 = xa * ha.w; \
                float pb0 = xb * hb.x, pb1 = xb * hb.y, pb2 = xb * hb.z, pb3 = xb * hb.w; \
                ah[p][mf][0] = pack_hi(pa0, pa1); ah[p][mf][1] = pack_hi(pb0, pb1); \
                ah[p][mf][2] = pack_hi(pa2, pa3); ah[p][mf][3] = pack_hi(pb2, pb3); \
                al[p][mf][0] = pack_lo(pa0, pa1); al[p][mf][1] = pack_lo(pb0, pb1); \
                al[p][mf][2] = pack_lo(pa2, pa3); al[p][mf][3] = pack_lo(pb2, pb3); \
            }                                                                 \
        }

#define MMA_STAGE(p)                                                          \
        {                                                                     \
            _Pragma("unroll")                                                 \
            for (int mf = 0; mf < 2; ++mf)                                    \
                _Pragma("unroll")                                             \
                for (int nf = 0; nf < 4; ++nf)                                \
                    mma16816(acc[mf][nf], ah[p][mf], Bf[p][nf].x, Bf[p][nf].y); \
            _Pragma("unroll")                                                 \
            for (int mf = 0; mf < 2; ++mf)                                    \
                _Pragma("unroll")                                             \
                for (int nf = 0; nf < 4; ++nf)                                \
                    mma16816(acc[mf][nf], ah[p][mf], Bf[p][nf].z, Bf[p][nf].w); \
            _Pragma("unroll")                                                 \
            for (int mf = 0; mf < 2; ++mf)                                    \
                _Pragma("unroll")                                             \
                for (int nf = 0; nf < 4; ++nf)                                \
                    mma16816(acc[mf][nf], al[p][mf], Bf[p][nf].x, Bf[p][nf].y); \
        }

        PREP_STAGE(0, 0)
        PREP_STAGE(1, 1)
        MMA_STAGE(0)
        PREP_STAGE(2, 0)
        MMA_STAGE(1)
        PREP_STAGE(3, 1)
        MMA_STAGE(0)
        MMA_STAGE(1)

#undef PREP_STAGE
#undef MMA_STAGE

        ++buf; if (buf >= 3) buf -= 3;
        // no end-of-chunk barrier: next chunk's cp.async targets a free buffer
    }

    // epilogue: hout[b][e][n] = acc + bias
#pragma unroll
    for (int mf = 0; mf < 2; ++mf) {
        const int ra = ra_base + mf * 16;
        const int gb = b0 + (ra >> 6);
        const int e  = ra & 63;
        float* p0 = hout + ((size_t)gb * 64 + e) * 64;
        float* p8 = hout + ((size_t)gb * 64 + e + 8) * 64;
#pragma unroll
        for (int nf = 0; nf < 4; ++nf) {
            const int n = wn * 32 + nf * 8 + q2;
            float bv0 = bias_s[n], bv1 = bias_s[n + 1];
            float2 v0 = make_float2(acc[mf][nf][0] + bv0, acc[mf][nf][1] + bv1);
            float2 v8 = make_float2(acc[mf][nf][2] + bv0, acc[mf][nf][3] + bv1);
            *(float2*)&p0[n] = v0;
            *(float2*)&p8[n] = v8;
        }
    }
}

// ---------------------------------------------------------------------------
// S kernel: S[b][i*FI+j] = sum_e x[b,i,e]*h[b,j,e].
// ---------------------------------------------------------------------------
template<int FI>
__global__ void __launch_bounds__(256)
skern(const float* __restrict__ x, const float* __restrict__ h,
      float* __restrict__ S)
{
    constexpr int FAN = 32 * FI;
    __shared__ float xs[32 * 65];
    __shared__ float hs[FI * 65];
    const int b = blockIdx.x, tid = threadIdx.x;

    for (int idx = tid; idx < 2048; idx += 256) {
        int i = idx >> 6, e = idx & 63;
        xs[i * 65 + e] = x[(b * 32 + i) * 64 + e];
    }
    if (FI == 32) {
        for (int idx = tid; idx < 2048; idx += 256) {
            int j = idx >> 6, e = idx & 63;
            hs[j * 65 + e] = h[(b * 32 + j) * 64 + e];
        }
    } else {
        for (int idx = tid; idx < 4096; idx += 256) {
            int j = idx & 63, e = idx >> 6;
            hs[j * 65 + e] = h[(b * 64 + e) * 64 + j];
        }
    }
    __syncthreads();

    constexpr int DJ = FI / 16;
    const int i0 = (tid >> 4) * 2;
    const int j0 = (tid & 15) * DJ;

    float acc[2][DJ];
#pragma unroll
    for (int di = 0; di < 2; ++di)
#pragma unroll
        for (int dj = 0; dj < DJ; ++dj) acc[di][dj] = 0.f;

#pragma unroll 4
    for (int e = 0; e < 64; ++e) {
        float x0 = xs[i0 * 65 + e];
        float x1 = xs[(i0 + 1) * 65 + e];
#pragma unroll
        for (int dj = 0; dj < DJ; ++dj) {
            float hv = hs[(j0 + dj) * 65 + e];
            acc[0][dj] += x0 * hv;
            acc[1][dj] += x1 * hv;
        }
    }
#pragma unroll
    for (int di = 0; di < 2; ++di)
#pragma unroll
        for (int dj = 0; dj < DJ; ++dj)
            S[(size_t)b * FAN + (i0 + di) * FI + (j0 + dj)] = acc[di][dj];
}

// ---------------------------------------------------------------------------
template<int FAN>
__global__ void __launch_bounds__(256)
dgemm(const float* __restrict__ S, const float* __restrict__ W,
      float* __restrict__ part, int koff, int outoff)
{
    constexpr int KSL = FAN / 8;
    __shared__ float Sm[128 * 68];
    __shared__ float Wt[64 * 33];
    const int tid = threadIdx.x;
    const int m0 = blockIdx.x * 128, n0 = blockIdx.y * 32;
    const int k0 = blockIdx.z * KSL;
    const int ty = tid >> 3, tx = tid & 7;

    float acc[4][4];
#pragma unroll
    for (int r = 0; r < 4; ++r)
#pragma unroll
        for (int cn = 0; cn < 4; ++cn) acc[r][cn] = 0.f;

    for (int kc = 0; kc < KSL; kc += 64) {
        __syncthreads();
#pragma unroll
        for (int r = 0; r < 8; ++r) {
            int idx = tid + r * 256;
            int m = idx >> 4, kq = idx & 15;
            *(float4*)&Sm[m * 68 + kq * 4] =
                *(const float4*)&S[(size_t)(m0 + m) * FAN + k0 + kc + kq * 4];
        }
#pragma unroll
        for (int r = 0; r < 8; ++r) {
            int idx = tid + r * 256;
            int kk = idx >> 5, n = idx & 31;
            Wt[kk * 33 + n] = W[(size_t)(k0 + kc + kk) * 128 + koff + n0 + n];
        }
        __syncthreads();
#pragma unroll 4
        for (int k = 0; k < 64; ++k) {
            float a[4], bb[4];
#pragma unroll
            for (int r = 0; r < 4; ++r) a[r] = Sm[(ty * 4 + r) * 68 + k];
#pragma unroll
            for (int cn = 0; cn < 4; ++cn) bb[cn] = Wt[k * 33 + tx * 4 + cn];
#pragma unroll
            for (int r = 0; r < 4; ++r)
#pragma unroll
                for (int cn = 0; cn < 4; ++cn) acc[r][cn] += a[r] * bb[cn];
        }
    }

    float* pb = part + ((size_t)blockIdx.z * B_SZ) * 256;
#pragma unroll
    for (int r = 0; r < 4; ++r)
#pragma unroll
        for (int cn = 0; cn < 4; ++cn)
            pb[(size_t)(m0 + ty * 4 + r) * 256 + outoff + n0 + tx * 4 + cn] = acc[r][cn];
}

// ---------------------------------------------------------------------------
__global__ void __launch_bounds__(256)
reduce_out(const float* __restrict__ part, const float* __restrict__ b0,
           const float* __restrict__ b1, const float* __restrict__ b2,
           float* __restrict__ out)
{
    const int b = blockIdx.x, c = threadIdx.x;
    float v = (c < 64) ? b0[64 + c] : (c < 128) ? b1[c] : b2[c - 128];
    float s = 64.0f * v;
#pragma unroll
    for (int z = 0; z < 8; ++z)
        s += part[((size_t)z * B_SZ + b) * 256 + c];
    out[b * 256 + c] = s;
}

// ---------------------------------------------------------------------------
extern "C" void kernel_launch(void* const* d_in, const int* in_sizes, int n_in,
                              void* d_out, int out_size)
{
    const float* x  = (const float*)d_in[0];
    const float* W0 = (const float*)d_in[1];
    const float* b0 = (const float*)d_in[2];
    const float* W1 = (const float*)d_in[3];
    const float* b1 = (const float*)d_in[4];
    const float* W2 = (const float*)d_in[5];
    const float* b2 = (const float*)d_in[6];
    float* out = (float*)d_out;

    float *h1p, *h2p, *s0p, *s1p, *s2p, *pp;
    uint4 *wf0, *wf1;
    cudaGetSymbolAddress((void**)&h1p, g_h1);
    cudaGetSymbolAddress((void**)&h2p, g_h2);
    cudaGetSymbolAddress((void**)&wf0, g_Wf0);
    cudaGetSymbolAddress((void**)&wf1, g_Wf1);
    cudaGetSymbolAddress((void**)&s0p, g_S0);
    cudaGetSymbolAddress((void**)&s1p, g_S1);
    cudaGetSymbolAddress((void**)&s2p, g_S2);
    cudaGetSymbolAddress((void**)&pp,  g_part);

    const int smM = 256 + 128 * 33 * 4 + 128 * 80 * 4 + 3 * 16384;   // 107264
    cudaFuncSetAttribute(cin_mma<32>, cudaFuncAttributeMaxDynamicSharedMemorySize, smM);
    cudaFuncSetAttribute(cin_mma<64>, cudaFuncAttributeMaxDynamicSharedMemorySize, smM);

    wfrag<<<16, 256>>>(W0, wf0);
    wfrag<<<32, 256>>>(W1, wf1);

    cin_mma<32><<<512, 256, smM>>>(x, x,   wf0, b0, h1p);
    cin_mma<64><<<512, 256, smM>>>(x, h1p, wf1, b1, h2p);

    skern<32><<<B_SZ, 256>>>(x, x,   s0p);
    skern<64><<<B_SZ, 256>>>(x, h1p, s1p);
    skern<64><<<B_SZ, 256>>>(x, h2p, s2p);

    dgemm<1024><<<dim3(8, 2, 8), 256>>>(s0p, W0, pp, 64, 0);
    dgemm<2048><<<dim3(8, 2, 8), 256>>>(s1p, W1, pp, 64, 64);
    dgemm<2048><<<dim3(8, 4, 8), 256>>>(s2p, W2, pp, 0, 128);

    reduce_out<<<B_SZ, 256>>>(pp, b0, b1, b2, out);
}

// round 8
// speedup vs baseline: 1.0482x; 1.0482x over previous
#include <cuda_runtime.h>
#include <cuda_bf16.h>
#include <cstdint>

#define B_SZ 1024

// hidden activations, [b][e][j] layout
__device__ float g_h1[B_SZ * 64 * 64];
__device__ float g_h2[B_SZ * 64 * 64];
// W fragment-linear: per 64-K chunk: [s(4)][nfrag(8)][lane(32)] uint4{hi01,hi23,lo01,lo23}
__device__ __align__(16) uint4 g_Wf0[16 * 1024];
__device__ __align__(16) uint4 g_Wf1[32 * 1024];
// S matrices (direct path)
__device__ float g_S0[B_SZ * 1024];
__device__ float g_S1[B_SZ * 2048];
__device__ float g_S2[B_SZ * 2048];
// k-split partials: [z(16)][b][256]
__device__ float g_part[16 * B_SZ * 256];

__device__ __forceinline__ uint32_t pack_hi(float a, float b) {
    return __byte_perm(__float_as_uint(a), __float_as_uint(b), 0x7632);
}
__device__ __forceinline__ uint32_t pack_lo(float a, float b) {
    float la = a - __uint_as_float(__float_as_uint(a) & 0xFFFF0000u);
    float lb = b - __uint_as_float(__float_as_uint(b) & 0xFFFF0000u);
    uint32_t r;
    asm("cvt.rn.bf16x2.f32 %0, %1, %2;" : "=r"(r) : "f"(lb), "f"(la));
    return r;
}
__device__ __forceinline__ void mma16816(float* c, const uint32_t* a,
                                         uint32_t b0, uint32_t b1) {
    asm volatile(
        "mma.sync.aligned.m16n8k16.row.col.f32.bf16.bf16.f32 "
        "{%0,%1,%2,%3}, {%4,%5,%6,%7}, {%8,%9}, {%0,%1,%2,%3};"
        : "+f"(c[0]), "+f"(c[1]), "+f"(c[2]), "+f"(c[3])
        : "r"(a[0]), "r"(a[1]), "r"(a[2]), "r"(a[3]), "r"(b0), "r"(b1));
}

// ---------------------------------------------------------------------------
__global__ void __launch_bounds__(256)
wfrag(const float* __restrict__ W, uint4* __restrict__ out) {
    const int c = blockIdx.x;
    for (int t = threadIdx.x; t < 1024; t += 256) {
        int s = t >> 8, f = (t >> 5) & 7, lane = t & 31;
        int n = f * 8 + (lane >> 2);
        int r = c * 64 + s * 16 + (lane & 3) * 4;
        float w0 = W[(r    ) * 128 + n], w1 = W[(r + 1) * 128 + n];
        float w2 = W[(r + 2) * 128 + n], w3 = W[(r + 3) * 128 + n];
        uint4 o;
        o.x = pack_hi(w0, w1);
        o.y = pack_hi(w2, w3);
        o.z = pack_lo(w0, w1);
        o.w = pack_lo(w2, w3);
        out[c * 1024 + t] = o;
    }
}

// ---------------------------------------------------------------------------
// Hidden layer via mma.sync (bf16 split). M-tile = 64 rows = ONE batch/CTA.
// B fragments straight from L2 via __ldg (no B smem, no loop barriers).
// grid=1024, block=256 (8 warps = 4m x 2n), 3 CTAs/SM.
// ---------------------------------------------------------------------------
template<int FI>
__global__ void __launch_bounds__(256, 3)
cin_mma(const float* __restrict__ x, const float* __restrict__ h,
        const uint4* __restrict__ Wf, const float* __restrict__ bias,
        float* __restrict__ hout)
{
    constexpr int NC = (32 * FI) / 64;   // 16 or 32 chunks
    __shared__ float bias_s[64];
    __shared__ float xs[64 * 33];        // [e][i]
    __shared__ float hs[64 * 80];        // [e][j], 80-pad => conflict-free LDS.128

    const int tid  = threadIdx.x;
    const int lane = tid & 31;
    const int wid  = tid >> 5;
    const int wm   = wid & 3, wn = wid >> 2;
    const int tq   = lane & 3;
    const int b    = blockIdx.x;

    if (tid < 64) bias_s[tid] = bias[tid];
    for (int idx = tid; idx < 2048; idx += 256) {
        int i = idx >> 6, e = idx & 63;
        xs[e * 33 + i] = x[(b * 32 + i) * 64 + e];
    }
    if (FI == 64) {
#pragma unroll
        for (int r = 0; r < 4; ++r) {
            int idx = tid + r * 256;
            int row = idx >> 4, c4 = idx & 15;
            float4 v = *(const float4*)&h[((size_t)b * 64 + row) * 64 + c4 * 4];
            *(float4*)&hs[row * 80 + c4 * 4] = v;
        }
    } else {
#pragma unroll
        for (int r = 0; r < 8; ++r) {
            int idx = tid + r * 256;
            int j = idx >> 6, e = idx & 63;
            hs[e * 80 + j] = h[(b * 32 + j) * 64 + e];
        }
    }
    __syncthreads();   // the only barrier

    float acc[4][4];
#pragma unroll
    for (int nf = 0; nf < 4; ++nf)
#pragma unroll
        for (int r = 0; r < 4; ++r) acc[nf][r] = 0.f;

    const int ra = wm * 16 + (lane >> 2);   // 0..63
    const int rb = ra + 8;

    // B fragment base index helper: Wf[c*1024 + (s*8 + wn*4 + nf)*32 + lane]
    const uint4* Wl = Wf + wn * 128 + lane;

    uint4 Bf[4], Bn[4];
#pragma unroll
    for (int nf = 0; nf < 4; ++nf) Bf[nf] = __ldg(Wl + nf * 32);

    for (int t = 0; t < 4 * NC; ++t) {
        const int c = t >> 2, s = t & 3;
        // prefetch next stage's B
        const int tn = t + 1;
        if (tn < 4 * NC) {
            const uint4* p = Wl + (size_t)(tn >> 2) * 1024 + (tn & 3) * 256;
#pragma unroll
            for (int nf = 0; nf < 4; ++nf) Bn[nf] = __ldg(p + nf * 32);
        }

        const int icol = (FI == 64) ? c : (2 * c + (s >> 1));
        const int jcol = ((FI == 64) ? s * 16 : (s & 1) * 16) + 4 * tq;
        float xa = xs[ra * 33 + icol];
        float xb = xs[rb * 33 + icol];
        float4 ha = *(const float4*)&hs[ra * 80 + jcol];
        float4 hb = *(const float4*)&hs[rb * 80 + jcol];
        float pa0 = xa * ha.x, pa1 = xa * ha.y, pa2 = xa * ha.z, pa3 = xa * ha.w;
        float pb0 = xb * hb.x, pb1 = xb * hb.y, pb2 = xb * hb.z, pb3 = xb * hb.w;
        uint32_t ah[4], al[4];
        ah[0] = pack_hi(pa0, pa1); ah[1] = pack_hi(pb0, pb1);
        ah[2] = pack_hi(pa2, pa3); ah[3] = pack_hi(pb2, pb3);
        al[0] = pack_lo(pa0, pa1); al[1] = pack_lo(pb0, pb1);
        al[2] = pack_lo(pa2, pa3); al[3] = pack_lo(pb2, pb3);

#pragma unroll
        for (int nf = 0; nf < 4; ++nf) mma16816(acc[nf], ah, Bf[nf].x, Bf[nf].y);
#pragma unroll
        for (int nf = 0; nf < 4; ++nf) mma16816(acc[nf], ah, Bf[nf].z, Bf[nf].w);
#pragma unroll
        for (int nf = 0; nf < 4; ++nf) mma16816(acc[nf], al, Bf[nf].x, Bf[nf].y);

#pragma unroll
        for (int nf = 0; nf < 4; ++nf) Bf[nf] = Bn[nf];
    }

    // epilogue: hout[b][e][n] = acc + bias  (rows e=ra, e=ra+8)
    {
        float* p0 = hout + ((size_t)b * 64 + ra) * 64;
        float* p8 = hout + ((size_t)b * 64 + ra + 8) * 64;
#pragma unroll
        for (int nf = 0; nf < 4; ++nf) {
            const int n = wn * 32 + nf * 8 + tq * 2;
            float bv0 = bias_s[n], bv1 = bias_s[n + 1];
            *(float2*)&p0[n] = make_float2(acc[nf][0] + bv0, acc[nf][1] + bv1);
            *(float2*)&p8[n] = make_float2(acc[nf][2] + bv0, acc[nf][3] + bv1);
        }
    }
}

// ---------------------------------------------------------------------------
// S kernel: S[b][i*FI+j] = sum_e x[b,i,e]*h[b,j,e].
// ---------------------------------------------------------------------------
template<int FI>
__global__ void __launch_bounds__(256)
skern(const float* __restrict__ x, const float* __restrict__ h,
      float* __restrict__ S)
{
    constexpr int FAN = 32 * FI;
    __shared__ float xs[32 * 65];
    __shared__ float hs[FI * 65];
    const int b = blockIdx.x, tid = threadIdx.x;

    for (int idx = tid; idx < 2048; idx += 256) {
        int i = idx >> 6, e = idx & 63;
        xs[i * 65 + e] = x[(b * 32 + i) * 64 + e];
    }
    if (FI == 32) {
        for (int idx = tid; idx < 2048; idx += 256) {
            int j = idx >> 6, e = idx & 63;
            hs[j * 65 + e] = h[(b * 32 + j) * 64 + e];
        }
    } else {
        for (int idx = tid; idx < 4096; idx += 256) {
            int j = idx & 63, e = idx >> 6;
            hs[j * 65 + e] = h[(b * 64 + e) * 64 + j];
        }
    }
    __syncthreads();

    constexpr int DJ = FI / 16;
    const int i0 = (tid >> 4) * 2;
    const int j0 = (tid & 15) * DJ;

    float acc[2][DJ];
#pragma unroll
    for (int di = 0; di < 2; ++di)
#pragma unroll
        for (int dj = 0; dj < DJ; ++dj) acc[di][dj] = 0.f;

#pragma unroll 4
    for (int e = 0; e < 64; ++e) {
        float x0 = xs[i0 * 65 + e];
        float x1 = xs[(i0 + 1) * 65 + e];
#pragma unroll
        for (int dj = 0; dj < DJ; ++dj) {
            float hv = hs[(j0 + dj) * 65 + e];
            acc[0][dj] += x0 * hv;
            acc[1][dj] += x1 * hv;
        }
    }
#pragma unroll
    for (int di = 0; di < 2; ++di)
#pragma unroll
        for (int dj = 0; dj < DJ; ++dj)
            S[(size_t)b * FAN + (i0 + di) * FI + (j0 + dj)] = acc[di][dj];
}

// ---------------------------------------------------------------------------
// Direct GEMM, deterministic 16-way k-split.
// ---------------------------------------------------------------------------
template<int FAN>
__global__ void __launch_bounds__(256)
dgemm(const float* __restrict__ S, const float* __restrict__ W,
      float* __restrict__ part, int koff, int outoff)
{
    constexpr int KSL = FAN / 16;
    __shared__ float Sm[128 * 68];
    __shared__ float Wt[64 * 33];
    const int tid = threadIdx.x;
    const int m0 = blockIdx.x * 128, n0 = blockIdx.y * 32;
    const int k0 = blockIdx.z * KSL;
    const int ty = tid >> 3, tx = tid & 7;

    float acc[4][4];
#pragma unroll
    for (int r = 0; r < 4; ++r)
#pragma unroll
        for (int cn = 0; cn < 4; ++cn) acc[r][cn] = 0.f;

    for (int kc = 0; kc < KSL; kc += 64) {
        __syncthreads();
#pragma unroll
        for (int r = 0; r < 8; ++r) {
            int idx = tid + r * 256;
            int m = idx >> 4, kq = idx & 15;
            *(float4*)&Sm[m * 68 + kq * 4] =
                *(const float4*)&S[(size_t)(m0 + m) * FAN + k0 + kc + kq * 4];
        }
#pragma unroll
        for (int r = 0; r < 8; ++r) {
            int idx = tid + r * 256;
            int kk = idx >> 5, n = idx & 31;
            Wt[kk * 33 + n] = W[(size_t)(k0 + kc + kk) * 128 + koff + n0 + n];
        }
        __syncthreads();
#pragma unroll 4
        for (int k = 0; k < 64; ++k) {
            float a[4], bb[4];
#pragma unroll
            for (int r = 0; r < 4; ++r) a[r] = Sm[(ty * 4 + r) * 68 + k];
#pragma unroll
            for (int cn = 0; cn < 4; ++cn) bb[cn] = Wt[k * 33 + tx * 4 + cn];
#pragma unroll
            for (int r = 0; r < 4; ++r)
#pragma unroll
                for (int cn = 0; cn < 4; ++cn) acc[r][cn] += a[r] * bb[cn];
        }
    }

    float* pb = part + ((size_t)blockIdx.z * B_SZ) * 256;
#pragma unroll
    for (int r = 0; r < 4; ++r)
#pragma unroll
        for (int cn = 0; cn < 4; ++cn)
            pb[(size_t)(m0 + ty * 4 + r) * 256 + outoff + n0 + tx * 4 + cn] = acc[r][cn];
}

// ---------------------------------------------------------------------------
__global__ void __launch_bounds__(256)
reduce_out(const float* __restrict__ part, const float* __restrict__ b0,
           const float* __restrict__ b1, const float* __restrict__ b2,
           float* __restrict__ out)
{
    const int b = blockIdx.x, c = threadIdx.x;
    float v = (c < 64) ? b0[64 + c] : (c < 128) ? b1[c] : b2[c - 128];
    float s = 64.0f * v;
#pragma unroll
    for (int z = 0; z < 16; ++z)
        s += part[((size_t)z * B_SZ + b) * 256 + c];
    out[b * 256 + c] = s;
}

// ---------------------------------------------------------------------------
extern "C" void kernel_launch(void* const* d_in, const int* in_sizes, int n_in,
                              void* d_out, int out_size)
{
    const float* x  = (const float*)d_in[0];
    const float* W0 = (const float*)d_in[1];
    const float* b0 = (const float*)d_in[2];
    const float* W1 = (const float*)d_in[3];
    const float* b1 = (const float*)d_in[4];
    const float* W2 = (const float*)d_in[5];
    const float* b2 = (const float*)d_in[6];
    float* out = (float*)d_out;

    float *h1p, *h2p, *s0p, *s1p, *s2p, *pp;
    uint4 *wf0, *wf1;
    cudaGetSymbolAddress((void**)&h1p, g_h1);
    cudaGetSymbolAddress((void**)&h2p, g_h2);
    cudaGetSymbolAddress((void**)&wf0, g_Wf0);
    cudaGetSymbolAddress((void**)&wf1, g_Wf1);
    cudaGetSymbolAddress((void**)&s0p, g_S0);
    cudaGetSymbolAddress((void**)&s1p, g_S1);
    cudaGetSymbolAddress((void**)&s2p, g_S2);
    cudaGetSymbolAddress((void**)&pp,  g_part);

    wfrag<<<16, 256>>>(W0, wf0);
    wfrag<<<32, 256>>>(W1, wf1);

    cin_mma<32><<<B_SZ, 256>>>(x, x,   wf0, b0, h1p);
    cin_mma<64><<<B_SZ, 256>>>(x, h1p, wf1, b1, h2p);

    skern<32><<<B_SZ, 256>>>(x, x,   s0p);
    skern<64><<<B_SZ, 256>>>(x, h1p, s1p);
    skern<64><<<B_SZ, 256>>>(x, h2p, s2p);

    dgemm<1024><<<dim3(8, 2, 16), 256>>>(s0p, W0, pp, 64, 0);
    dgemm<2048><<<dim3(8, 2, 16), 256>>>(s1p, W1, pp, 64, 64);
    dgemm<2048><<<dim3(8, 4, 16), 256>>>(s2p, W2, pp, 0, 128);

    reduce_out<<<B_SZ, 256>>>(pp, b0, b1, b2, out);
}